// round 13
// baseline (speedup 1.0000x reference)
#include <cuda_runtime.h>
#include <cuda_fp16.h>
#include <math.h>
#include <stdint.h>

#define M_DIM 8192
#define N_DIM 3072
#define K_DIM 4096
#define PADN  4096

// Scratch (device globals; allocation-free)
__device__ float  g_y [(size_t)M_DIM * N_DIM];                 // 96 MB  (K-half 0 + bias)
__device__ float  g_y2[(size_t)M_DIM * N_DIM];                 // 96 MB  (K-half 1)
__device__ __half g_xs[2ull * (size_t)M_DIM * K_DIM];          // 128 MB: X splits [s][m][k]
__device__ __half g_wt[2ull * (size_t)N_DIM * K_DIM];          // 48 MB:  (64*W)^T splits [s][n][k]

// ---------------------------------------------------------------------------
__device__ __forceinline__ uint32_t smem_u32(const void* p) {
    uint32_t a;
    asm("{ .reg .u64 t; cvta.to.shared.u64 t, %1; cvt.u32.u64 %0, t; }" : "=r"(a) : "l"(p));
    return a;
}
__device__ __forceinline__ void cpa16(uint32_t dst, const void* src) {
    asm volatile("cp.async.cg.shared.global [%0], [%1], 16;" :: "r"(dst), "l"(src) : "memory");
}
#define CP_COMMIT() asm volatile("cp.async.commit_group;" ::: "memory")

#define LDSM_X4(r, addr) \
    asm volatile("ldmatrix.sync.aligned.m8n8.x4.shared.b16 {%0,%1,%2,%3}, [%4];" \
        : "=r"((r)[0]), "=r"((r)[1]), "=r"((r)[2]), "=r"((r)[3]) : "r"(addr))

// fp16 mma, fp32 accumulate: d += a*b
#define MMA_F16(c, a, b0, b1) \
    asm volatile("mma.sync.aligned.m16n8k16.row.col.f32.f16.f16.f32 " \
        "{%0,%1,%2,%3}, {%4,%5,%6,%7}, {%8,%9}, {%0,%1,%2,%3};" \
        : "+f"((c)[0]), "+f"((c)[1]), "+f"((c)[2]), "+f"((c)[3]) \
        : "r"((a)[0]), "r"((a)[1]), "r"((a)[2]), "r"((a)[3]), "r"(b0), "r"(b1))

// fresh chunk: d = a*b + 0
#define MMA_F16_Z(d, a, b0, b1, z) \
    asm volatile("mma.sync.aligned.m16n8k16.row.col.f32.f16.f16.f32 " \
        "{%0,%1,%2,%3}, {%4,%5,%6,%7}, {%8,%9}, {%10,%10,%10,%10};" \
        : "=f"((d)[0]), "=f"((d)[1]), "=f"((d)[2]), "=f"((d)[3]) \
        : "r"((a)[0]), "r"((a)[1]), "r"((a)[2]), "r"((a)[3]), "r"(b0), "r"(b1), "f"(z))

// ---------------------------------------------------------------------------
// Merged prepass: blocks [0, 16384) split X -> 2 fp16 planes;
// blocks [16384, 28672) scale W by 64, split + transpose -> 2 fp16 planes.
// ---------------------------------------------------------------------------
#define XBLOCKS 16384
#define WBLOCKS (128 * 96)            // (K/32) x (N/32)

__global__ __launch_bounds__(256)
void split_xw_kernel(const float* __restrict__ X, const float* __restrict__ W)
{
    __shared__ __half sh[2][32][33];
    const int bid = blockIdx.x;
    const int tid = threadIdx.x;

    if (bid < XBLOCKS) {
        size_t idx = ((size_t)bid * 256 + tid) * 8;
        float4 v0 = *(const float4*)(X + idx);
        float4 v1 = *(const float4*)(X + idx + 4);
        float f[8] = {v0.x, v0.y, v0.z, v0.w, v1.x, v1.y, v1.z, v1.w};
        __half2 p0[4], p1[4];
#pragma unroll
        for (int j = 0; j < 4; j++) {
            float a = f[2*j], b = f[2*j+1];
            __half a0 = __float2half_rn(a), b0 = __float2half_rn(b);
            float ra = a - __half2float(a0), rb = b - __half2float(b0);
            __half a1 = __float2half_rn(ra), b1 = __float2half_rn(rb);
            p0[j] = __halves2half2(a0, b0);
            p1[j] = __halves2half2(a1, b1);
        }
        const size_t MK = (size_t)M_DIM * K_DIM;
        *(float4*)(g_xs + 0 * MK + idx) = *(float4*)p0;
        *(float4*)(g_xs + 1 * MK + idx) = *(float4*)p1;
    } else {
        const int wb = bid - XBLOCKS;
        const int k0 = (wb & 127) * 32;           // 128 k-tiles
        const int n0 = (wb >> 7) * 32;            // 96 n-tiles
        const int tx = tid & 31, ty = tid >> 5;
#pragma unroll
        for (int r = 0; r < 4; r++) {
            int kk = ty + r * 8;
            float w = W[(size_t)(k0 + kk) * N_DIM + n0 + tx] * 64.0f;  // exact scale
            __half b0 = __float2half_rn(w);
            float r1 = w - __half2float(b0);
            __half b1 = __float2half_rn(r1);
            sh[0][kk][tx] = b0; sh[1][kk][tx] = b1;
        }
        __syncthreads();
        const size_t NK = (size_t)N_DIM * K_DIM;
#pragma unroll
        for (int s = 0; s < 2; s++)
#pragma unroll
            for (int r = 0; r < 4; r++) {
                int nn = ty + r * 8;
                g_wt[(size_t)s * NK + (size_t)(n0 + nn) * K_DIM + k0 + tx] = sh[s][tx][nn];
            }
    }
}

// ---------------------------------------------------------------------------
// GEMM: fp16x2 via mma.sync.m16n8k16, 3 accumulating passes per k16 chunk
// (small passes first, main pass last), RN FADD drain into fp32 masters.
// 128x128 tile, BK=64, 256 threads (8 warps, 4Mx2N), 3-stage cp.async
// pipeline, SPLIT-K=2 (blockIdx.z selects K half; half 1 -> g_y2, no bias).
// ---------------------------------------------------------------------------
#define GKT 64
#define NKITER_H 32                   // K-tiles per K-half (K/2/GKT)
#define TILE_B 16384                  // 128 rows x 64 fp16 (128B rows, SW128)
#define STG_B  (4 * TILE_B)           // 64 KB (A0,A1,B0,B1)
#define NSTAGE 3
#define DSMEM  (NSTAGE * STG_B)       // 192 KB

__device__ __forceinline__ void load_stage(uint32_t sb, int buf, int kt,
                                           int m0, int bn0, int tid)
{
    const int k0 = kt * GKT;
    const uint32_t base = sb + buf * STG_B;
    const size_t MK = (size_t)M_DIM * K_DIM;
    const size_t NK = (size_t)N_DIM * K_DIM;
#pragma unroll
    for (int t = 0; t < 4; t++) {
        const __half* src = (t < 2)
            ? (g_xs + (size_t)t * MK + (size_t)m0 * K_DIM + k0)
            : (g_wt + (size_t)(t - 2) * NK + (size_t)bn0 * K_DIM + k0);
        const uint32_t tb = base + t * TILE_B;
#pragma unroll
        for (int c = 0; c < 4; c++) {
            int chunk = tid + c * 256;           // 0..1023
            int row = chunk >> 3;
            int c16 = chunk & 7;
            uint32_t off = (uint32_t)(row * 128 + c16 * 16);
            uint32_t sw = off ^ ((off >> 3) & 0x70);   // SW128
            cpa16(tb + sw, src + (size_t)row * K_DIM + c16 * 8);
        }
    }
    CP_COMMIT();
}

__device__ __forceinline__ uint32_t lm_addr(uint32_t tbase, int row, int kbyte) {
    uint32_t off = (uint32_t)(row * 128 + kbyte);
    return tbase + (off ^ ((off >> 3) & 0x70));
}

__global__ __launch_bounds__(256, 1)
void gemm_fp16x2(const float* __restrict__ Bias)
{
    extern __shared__ char dsm[];
    const int tid = threadIdx.x;
    const int wid = tid >> 5, lid = tid & 31;
    const int wm = wid & 3;            // 4 warps down M (32 rows each)
    const int wn = wid >> 2;           // 2 warps across N (64 cols each)
    const int m0  = blockIdx.y * 128;
    const int bn0 = blockIdx.x * 128;
    const int kh  = blockIdx.z;        // K half: 0 or 1
    const int kt0 = kh * NKITER_H;

    const uint32_t sb = smem_u32(dsm);

    load_stage(sb, 0, kt0 + 0, m0, bn0, tid);
    load_stage(sb, 1, kt0 + 1, m0, bn0, tid);

    float acc[2][8][4];
#pragma unroll
    for (int mb = 0; mb < 2; mb++)
#pragma unroll
        for (int nb = 0; nb < 8; nb++)
#pragma unroll
            for (int q = 0; q < 4; q++) acc[mb][nb][q] = 0.0f;

    const float fzero = 0.0f;

    const int g = lid >> 3, r = lid & 7;
    const int a_row = wm * 32 + (g & 1) * 8 + r;   // + mb*16
    const int a_kg  = (g >> 1) * 16;               // + kb
    const int b_row = wn * 64 + (g >> 1) * 8 + r;  // + np*16
    const int b_kg  = (g & 1) * 16;                // + kb

    for (int i = 0; i < NKITER_H; i++) {
        const int buf = i % NSTAGE;
        if (i < NKITER_H - 1) asm volatile("cp.async.wait_group 1;" ::: "memory");
        else                  asm volatile("cp.async.wait_group 0;" ::: "memory");
        __syncthreads();

        if (i + 2 < NKITER_H) load_stage(sb, (i + 2) % NSTAGE, kt0 + i + 2, m0, bn0, tid);

        const uint32_t base = sb + buf * STG_B;

#pragma unroll
        for (int k16 = 0; k16 < 4; k16++) {
            const int kb = k16 * 32;               // bytes
            uint32_t af[2][2][4], bfr[2][4][4];
#pragma unroll
            for (int s = 0; s < 2; s++) {
#pragma unroll
                for (int mb = 0; mb < 2; mb++)
                    LDSM_X4(af[s][mb], lm_addr(base + s * TILE_B,
                                               a_row + mb * 16, kb + a_kg));
#pragma unroll
                for (int np = 0; np < 4; np++)
                    LDSM_X4(bfr[s][np], lm_addr(base + (2 + s) * TILE_B,
                                                b_row + np * 16, kb + b_kg));
            }
#pragma unroll
            for (int mb = 0; mb < 2; mb++)
#pragma unroll
                for (int np = 0; np < 4; np++) {
                    float ch[8];
                    // pass order: (x0,w1), (x1,w0), then main (x0,w0) LAST
                    MMA_F16_Z(ch,     af[0][mb], bfr[1][np][0], bfr[1][np][1], fzero);
                    MMA_F16_Z(ch + 4, af[0][mb], bfr[1][np][2], bfr[1][np][3], fzero);
                    MMA_F16(ch,     af[1][mb], bfr[0][np][0], bfr[0][np][1]);
                    MMA_F16(ch + 4, af[1][mb], bfr[0][np][2], bfr[0][np][3]);
                    MMA_F16(ch,     af[0][mb], bfr[0][np][0], bfr[0][np][1]);
                    MMA_F16(ch + 4, af[0][mb], bfr[0][np][2], bfr[0][np][3]);
                    // RN drain into master accumulators
#pragma unroll
                    for (int q = 0; q < 4; q++) {
                        acc[mb][2*np][q]     += ch[q];
                        acc[mb][2*np + 1][q] += ch[4 + q];
                    }
                }
        }
    }

    // Epilogue: undo W scale (exact /64); half 0 adds bias -> g_y, half 1 -> g_y2
    float* dstbuf = kh ? g_y2 : g_y;
    const int m0g = m0 + wm * 32;
    const int n0g = bn0 + wn * 64;
    const int cl = 2 * (lid & 3);
    const int rl = lid >> 2;
#pragma unroll
    for (int nb = 0; nb < 8; nb++) {
        const int col = n0g + nb * 8 + cl;
        float2 b2 = {0.0f, 0.0f};
        if (kh == 0) b2 = *(const float2*)(Bias + col);
#pragma unroll
        for (int mb = 0; mb < 2; mb++) {
            const int row = m0g + mb * 16 + rl;
            float2 v0 = { acc[mb][nb][0] * 0.015625f + b2.x,
                          acc[mb][nb][1] * 0.015625f + b2.y };
            float2 v1 = { acc[mb][nb][2] * 0.015625f + b2.x,
                          acc[mb][nb][3] * 0.015625f + b2.y };
            *(float2*)&dstbuf[(size_t)row * N_DIM + col]       = v0;
            *(float2*)&dstbuf[(size_t)(row + 8) * N_DIM + col] = v1;
        }
    }
}

// ---------------------------------------------------------------------------
// Radix-16 FWHT(4096) -> quantize -> FWHT(4096) -> slice 3072.
// Loads combine the two split-K halves: y = g_y + g_y2 (RN).
// launch_bounds(256, 8) caps regs at 32 to restore ~93% occupancy
// (round-10 measured regs=40 -> occ 71%, latency-bound).
// ---------------------------------------------------------------------------
__device__ __forceinline__ void fwht16_regs(float v[16]) {
#pragma unroll
    for (int h = 1; h < 16; h <<= 1) {
#pragma unroll
        for (int p = 0; p < 8; p++) {
            int i = ((p & ~(h - 1)) << 1) | (p & (h - 1));
            float a = v[i], c = v[i + h];
            v[i] = a + c;
            v[i + h] = a - c;
        }
    }
}

__global__ __launch_bounds__(256, 8)
void fwht_quant_kernel(float* __restrict__ out)
{
    __shared__ float sh[4352];          // 4096 + 256 pad
    const int row = blockIdx.x;
    const int tid = threadIdx.x;
    const float* yrow0 = g_y  + (size_t)row * N_DIM;
    const float* yrow1 = g_y2 + (size_t)row * N_DIM;

    float v[16];

    // ---- FWHT #1 ----
    if (tid < 192) {
#pragma unroll
        for (int j = 0; j < 16; j += 4) {
            float4 t4 = *(const float4*)(yrow0 + tid * 16 + j);
            float4 u4 = *(const float4*)(yrow1 + tid * 16 + j);
            v[j]   = t4.x + u4.x; v[j+1] = t4.y + u4.y;
            v[j+2] = t4.z + u4.z; v[j+3] = t4.w + u4.w;
        }
    } else {
#pragma unroll
        for (int j = 0; j < 16; j++) v[j] = 0.0f;
    }
    fwht16_regs(v);

    const int wbase = tid * 17;
#pragma unroll
    for (int j = 0; j < 16; j++) sh[wbase + j] = v[j];
    __syncthreads();

    const int a = tid >> 4, c = tid & 15;
    const int r2base = a * 272 + c;
#pragma unroll
    for (int j = 0; j < 16; j++) v[j] = sh[r2base + j * 17];
    fwht16_regs(v);
#pragma unroll
    for (int j = 0; j < 16; j++) sh[r2base + j * 17] = v[j];
    __syncthreads();

    const int r3base = (tid >> 4) * 17 + c;
#pragma unroll
    for (int j = 0; j < 16; j++) v[j] = sh[r3base + j * 272];
    fwht16_regs(v);

    // quantize in registers
#pragma unroll
    for (int j = 0; j < 16; j++) {
        float z = v[j] * 0.015625f;
        float t = rintf(z * 4.0f);
        t = fminf(7.0f, fmaxf(-8.0f, t));
        v[j] = t * 0.25f;
    }

    // ---- FWHT #2 ----
#pragma unroll
    for (int j = 0; j < 16; j++) sh[r3base + j * 272] = v[j];
    __syncthreads();

#pragma unroll
    for (int j = 0; j < 16; j++) v[j] = sh[wbase + j];
    fwht16_regs(v);
#pragma unroll
    for (int j = 0; j < 16; j++) sh[wbase + j] = v[j];
    __syncthreads();

#pragma unroll
    for (int j = 0; j < 16; j++) v[j] = sh[r2base + j * 17];
    fwht16_regs(v);
#pragma unroll
    for (int j = 0; j < 16; j++) sh[r2base + j * 17] = v[j];
    __syncthreads();

#pragma unroll
    for (int j = 0; j < 16; j++) v[j] = sh[r3base + j * 272];
    fwht16_regs(v);

    float* orow = out + (size_t)row * N_DIM;
#pragma unroll
    for (int j = 0; j < 12; j++)                      // 12*256 = 3072
        orow[j * 256 + tid] = v[j] * 0.015625f;
}

// ---------------------------------------------------------------------------
extern "C" void kernel_launch(void* const* d_in, const int* in_sizes, int n_in,
                              void* d_out, int out_size)
{
    const float* x = (const float*)d_in[0];   // (4,2048,4096) f32
    const float* W = (const float*)d_in[1];   // (4096,3072) f32
    const float* b = (const float*)d_in[2];   // (3072,) f32
    float* out = (float*)d_out;               // (4,2048,3072) f32

    cudaFuncSetAttribute(gemm_fp16x2, cudaFuncAttributeMaxDynamicSharedMemorySize, DSMEM);

    split_xw_kernel<<<XBLOCKS + WBLOCKS, 256>>>(x, W);
    gemm_fp16x2<<<dim3(N_DIM / 128, M_DIM / 128, 2), 256, DSMEM>>>(b);
    fwht_quant_kernel<<<M_DIM, 256>>>(out);
}

// round 14
// speedup vs baseline: 1.0007x; 1.0007x over previous
#include <cuda_runtime.h>
#include <cuda_fp16.h>
#include <math.h>
#include <stdint.h>

#define M_DIM 8192
#define N_DIM 3072
#define K_DIM 4096
#define PADN  4096

// Scratch (device globals; allocation-free)
__device__ float  g_y [(size_t)M_DIM * N_DIM];                 // 96 MB  (K-half 0 + bias)
__device__ float  g_y2[(size_t)M_DIM * N_DIM];                 // 96 MB  (K-half 1)
__device__ __half g_xs[2ull * (size_t)M_DIM * K_DIM];          // 128 MB: X splits [s][m][k]
__device__ __half g_wt[2ull * (size_t)N_DIM * K_DIM];          // 48 MB:  (64*W)^T splits [s][n][k]

// ---------------------------------------------------------------------------
__device__ __forceinline__ uint32_t smem_u32(const void* p) {
    uint32_t a;
    asm("{ .reg .u64 t; cvta.to.shared.u64 t, %1; cvt.u32.u64 %0, t; }" : "=r"(a) : "l"(p));
    return a;
}
__device__ __forceinline__ void cpa16(uint32_t dst, const void* src) {
    asm volatile("cp.async.cg.shared.global [%0], [%1], 16;" :: "r"(dst), "l"(src) : "memory");
}
#define CP_COMMIT() asm volatile("cp.async.commit_group;" ::: "memory")

#define LDSM_X4(r, addr) \
    asm volatile("ldmatrix.sync.aligned.m8n8.x4.shared.b16 {%0,%1,%2,%3}, [%4];" \
        : "=r"((r)[0]), "=r"((r)[1]), "=r"((r)[2]), "=r"((r)[3]) : "r"(addr))

// fp16 mma, fp32 accumulate: d += a*b
#define MMA_F16(c, a, b0, b1) \
    asm volatile("mma.sync.aligned.m16n8k16.row.col.f32.f16.f16.f32 " \
        "{%0,%1,%2,%3}, {%4,%5,%6,%7}, {%8,%9}, {%0,%1,%2,%3};" \
        : "+f"((c)[0]), "+f"((c)[1]), "+f"((c)[2]), "+f"((c)[3]) \
        : "r"((a)[0]), "r"((a)[1]), "r"((a)[2]), "r"((a)[3]), "r"(b0), "r"(b1))

// fresh chunk: d = a*b + 0
#define MMA_F16_Z(d, a, b0, b1, z) \
    asm volatile("mma.sync.aligned.m16n8k16.row.col.f32.f16.f16.f32 " \
        "{%0,%1,%2,%3}, {%4,%5,%6,%7}, {%8,%9}, {%10,%10,%10,%10};" \
        : "=f"((d)[0]), "=f"((d)[1]), "=f"((d)[2]), "=f"((d)[3]) \
        : "r"((a)[0]), "r"((a)[1]), "r"((a)[2]), "r"((a)[3]), "r"(b0), "r"(b1), "f"(z))

// ---------------------------------------------------------------------------
// Merged prepass: blocks [0, 16384) split X -> 2 fp16 planes;
// blocks [16384, 28672) scale W by 64, split + transpose -> 2 fp16 planes.
// ---------------------------------------------------------------------------
#define XBLOCKS 16384
#define WBLOCKS (128 * 96)            // (K/32) x (N/32)

__global__ __launch_bounds__(256)
void split_xw_kernel(const float* __restrict__ X, const float* __restrict__ W)
{
    __shared__ __half sh[2][32][33];
    const int bid = blockIdx.x;
    const int tid = threadIdx.x;

    if (bid < XBLOCKS) {
        size_t idx = ((size_t)bid * 256 + tid) * 8;
        float4 v0 = *(const float4*)(X + idx);
        float4 v1 = *(const float4*)(X + idx + 4);
        float f[8] = {v0.x, v0.y, v0.z, v0.w, v1.x, v1.y, v1.z, v1.w};
        __half2 p0[4], p1[4];
#pragma unroll
        for (int j = 0; j < 4; j++) {
            float a = f[2*j], b = f[2*j+1];
            __half a0 = __float2half_rn(a), b0 = __float2half_rn(b);
            float ra = a - __half2float(a0), rb = b - __half2float(b0);
            __half a1 = __float2half_rn(ra), b1 = __float2half_rn(rb);
            p0[j] = __halves2half2(a0, b0);
            p1[j] = __halves2half2(a1, b1);
        }
        const size_t MK = (size_t)M_DIM * K_DIM;
        *(float4*)(g_xs + 0 * MK + idx) = *(float4*)p0;
        *(float4*)(g_xs + 1 * MK + idx) = *(float4*)p1;
    } else {
        const int wb = bid - XBLOCKS;
        const int k0 = (wb & 127) * 32;           // 128 k-tiles
        const int n0 = (wb >> 7) * 32;            // 96 n-tiles
        const int tx = tid & 31, ty = tid >> 5;
#pragma unroll
        for (int r = 0; r < 4; r++) {
            int kk = ty + r * 8;
            float w = W[(size_t)(k0 + kk) * N_DIM + n0 + tx] * 64.0f;  // exact scale
            __half b0 = __float2half_rn(w);
            float r1 = w - __half2float(b0);
            __half b1 = __float2half_rn(r1);
            sh[0][kk][tx] = b0; sh[1][kk][tx] = b1;
        }
        __syncthreads();
        const size_t NK = (size_t)N_DIM * K_DIM;
#pragma unroll
        for (int s = 0; s < 2; s++)
#pragma unroll
            for (int r = 0; r < 4; r++) {
                int nn = ty + r * 8;
                g_wt[(size_t)s * NK + (size_t)(n0 + nn) * K_DIM + k0 + tx] = sh[s][tx][nn];
            }
    }
}

// ---------------------------------------------------------------------------
// GEMM: fp16x2 via mma.sync.m16n8k16, 3 accumulating passes per k16 chunk
// (small passes first, main pass last), RN FADD drain into fp32 masters.
// 128x128 tile, BK=64, 256 threads (8 warps, 4Mx2N), 3-stage cp.async
// pipeline, SPLIT-K=2 (blockIdx.z selects K half; half 1 -> g_y2, no bias).
// ---------------------------------------------------------------------------
#define GKT 64
#define NKITER_H 32                   // K-tiles per K-half (K/2/GKT)
#define TILE_B 16384                  // 128 rows x 64 fp16 (128B rows, SW128)
#define STG_B  (4 * TILE_B)           // 64 KB (A0,A1,B0,B1)
#define NSTAGE 3
#define DSMEM  (NSTAGE * STG_B)       // 192 KB

__device__ __forceinline__ void load_stage(uint32_t sb, int buf, int kt,
                                           int m0, int bn0, int tid)
{
    const int k0 = kt * GKT;
    const uint32_t base = sb + buf * STG_B;
    const size_t MK = (size_t)M_DIM * K_DIM;
    const size_t NK = (size_t)N_DIM * K_DIM;
#pragma unroll
    for (int t = 0; t < 4; t++) {
        const __half* src = (t < 2)
            ? (g_xs + (size_t)t * MK + (size_t)m0 * K_DIM + k0)
            : (g_wt + (size_t)(t - 2) * NK + (size_t)bn0 * K_DIM + k0);
        const uint32_t tb = base + t * TILE_B;
#pragma unroll
        for (int c = 0; c < 4; c++) {
            int chunk = tid + c * 256;           // 0..1023
            int row = chunk >> 3;
            int c16 = chunk & 7;
            uint32_t off = (uint32_t)(row * 128 + c16 * 16);
            uint32_t sw = off ^ ((off >> 3) & 0x70);   // SW128
            cpa16(tb + sw, src + (size_t)row * K_DIM + c16 * 8);
        }
    }
    CP_COMMIT();
}

__device__ __forceinline__ uint32_t lm_addr(uint32_t tbase, int row, int kbyte) {
    uint32_t off = (uint32_t)(row * 128 + kbyte);
    return tbase + (off ^ ((off >> 3) & 0x70));
}

__global__ __launch_bounds__(256, 1)
void gemm_fp16x2(const float* __restrict__ Bias)
{
    extern __shared__ char dsm[];
    const int tid = threadIdx.x;
    const int wid = tid >> 5, lid = tid & 31;
    const int wm = wid & 3;            // 4 warps down M (32 rows each)
    const int wn = wid >> 2;           // 2 warps across N (64 cols each)
    const int m0  = blockIdx.y * 128;
    const int bn0 = blockIdx.x * 128;
    const int kh  = blockIdx.z;        // K half: 0 or 1
    const int kt0 = kh * NKITER_H;

    const uint32_t sb = smem_u32(dsm);

    load_stage(sb, 0, kt0 + 0, m0, bn0, tid);
    load_stage(sb, 1, kt0 + 1, m0, bn0, tid);

    float acc[2][8][4];
#pragma unroll
    for (int mb = 0; mb < 2; mb++)
#pragma unroll
        for (int nb = 0; nb < 8; nb++)
#pragma unroll
            for (int q = 0; q < 4; q++) acc[mb][nb][q] = 0.0f;

    const float fzero = 0.0f;

    const int g = lid >> 3, r = lid & 7;
    const int a_row = wm * 32 + (g & 1) * 8 + r;   // + mb*16
    const int a_kg  = (g >> 1) * 16;               // + kb
    const int b_row = wn * 64 + (g >> 1) * 8 + r;  // + np*16
    const int b_kg  = (g & 1) * 16;                // + kb

    for (int i = 0; i < NKITER_H; i++) {
        const int buf = i % NSTAGE;
        if (i < NKITER_H - 1) asm volatile("cp.async.wait_group 1;" ::: "memory");
        else                  asm volatile("cp.async.wait_group 0;" ::: "memory");
        __syncthreads();

        if (i + 2 < NKITER_H) load_stage(sb, (i + 2) % NSTAGE, kt0 + i + 2, m0, bn0, tid);

        const uint32_t base = sb + buf * STG_B;

#pragma unroll
        for (int k16 = 0; k16 < 4; k16++) {
            const int kb = k16 * 32;               // bytes
            uint32_t af[2][2][4], bfr[2][4][4];
#pragma unroll
            for (int s = 0; s < 2; s++) {
#pragma unroll
                for (int mb = 0; mb < 2; mb++)
                    LDSM_X4(af[s][mb], lm_addr(base + s * TILE_B,
                                               a_row + mb * 16, kb + a_kg));
#pragma unroll
                for (int np = 0; np < 4; np++)
                    LDSM_X4(bfr[s][np], lm_addr(base + (2 + s) * TILE_B,
                                                b_row + np * 16, kb + b_kg));
            }
#pragma unroll
            for (int mb = 0; mb < 2; mb++)
#pragma unroll
                for (int np = 0; np < 4; np++) {
                    float ch[8];
                    // pass order: (x0,w1), (x1,w0), then main (x0,w0) LAST
                    MMA_F16_Z(ch,     af[0][mb], bfr[1][np][0], bfr[1][np][1], fzero);
                    MMA_F16_Z(ch + 4, af[0][mb], bfr[1][np][2], bfr[1][np][3], fzero);
                    MMA_F16(ch,     af[1][mb], bfr[0][np][0], bfr[0][np][1]);
                    MMA_F16(ch + 4, af[1][mb], bfr[0][np][2], bfr[0][np][3]);
                    MMA_F16(ch,     af[0][mb], bfr[0][np][0], bfr[0][np][1]);
                    MMA_F16(ch + 4, af[0][mb], bfr[0][np][2], bfr[0][np][3]);
                    // RN drain into master accumulators
#pragma unroll
                    for (int q = 0; q < 4; q++) {
                        acc[mb][2*np][q]     += ch[q];
                        acc[mb][2*np + 1][q] += ch[4 + q];
                    }
                }
        }
    }

    // Epilogue: undo W scale (exact /64); half 0 adds bias -> g_y, half 1 -> g_y2
    float* dstbuf = kh ? g_y2 : g_y;
    const int m0g = m0 + wm * 32;
    const int n0g = bn0 + wn * 64;
    const int cl = 2 * (lid & 3);
    const int rl = lid >> 2;
#pragma unroll
    for (int nb = 0; nb < 8; nb++) {
        const int col = n0g + nb * 8 + cl;
        float2 b2 = {0.0f, 0.0f};
        if (kh == 0) b2 = *(const float2*)(Bias + col);
#pragma unroll
        for (int mb = 0; mb < 2; mb++) {
            const int row = m0g + mb * 16 + rl;
            float2 v0 = { acc[mb][nb][0] * 0.015625f + b2.x,
                          acc[mb][nb][1] * 0.015625f + b2.y };
            float2 v1 = { acc[mb][nb][2] * 0.015625f + b2.x,
                          acc[mb][nb][3] * 0.015625f + b2.y };
            *(float2*)&dstbuf[(size_t)row * N_DIM + col]       = v0;
            *(float2*)&dstbuf[(size_t)(row + 8) * N_DIM + col] = v1;
        }
    }
}

// ---------------------------------------------------------------------------
// Radix-16 FWHT(4096) -> quantize -> FWHT(4096) -> slice 3072.
// Loads combine the two split-K halves: y = g_y + g_y2 (RN).
// launch_bounds(256, 8) caps regs at 32 to restore ~93% occupancy
// (round-10 measured regs=40 -> occ 71%, latency-bound).
// ---------------------------------------------------------------------------
__device__ __forceinline__ void fwht16_regs(float v[16]) {
#pragma unroll
    for (int h = 1; h < 16; h <<= 1) {
#pragma unroll
        for (int p = 0; p < 8; p++) {
            int i = ((p & ~(h - 1)) << 1) | (p & (h - 1));
            float a = v[i], c = v[i + h];
            v[i] = a + c;
            v[i + h] = a - c;
        }
    }
}

__global__ __launch_bounds__(256, 8)
void fwht_quant_kernel(float* __restrict__ out)
{
    __shared__ float sh[4352];          // 4096 + 256 pad
    const int row = blockIdx.x;
    const int tid = threadIdx.x;
    const float* yrow0 = g_y  + (size_t)row * N_DIM;
    const float* yrow1 = g_y2 + (size_t)row * N_DIM;

    float v[16];

    // ---- FWHT #1 ----
    if (tid < 192) {
#pragma unroll
        for (int j = 0; j < 16; j += 4) {
            float4 t4 = *(const float4*)(yrow0 + tid * 16 + j);
            float4 u4 = *(const float4*)(yrow1 + tid * 16 + j);
            v[j]   = t4.x + u4.x; v[j+1] = t4.y + u4.y;
            v[j+2] = t4.z + u4.z; v[j+3] = t4.w + u4.w;
        }
    } else {
#pragma unroll
        for (int j = 0; j < 16; j++) v[j] = 0.0f;
    }
    fwht16_regs(v);

    const int wbase = tid * 17;
#pragma unroll
    for (int j = 0; j < 16; j++) sh[wbase + j] = v[j];
    __syncthreads();

    const int a = tid >> 4, c = tid & 15;
    const int r2base = a * 272 + c;
#pragma unroll
    for (int j = 0; j < 16; j++) v[j] = sh[r2base + j * 17];
    fwht16_regs(v);
#pragma unroll
    for (int j = 0; j < 16; j++) sh[r2base + j * 17] = v[j];
    __syncthreads();

    const int r3base = (tid >> 4) * 17 + c;
#pragma unroll
    for (int j = 0; j < 16; j++) v[j] = sh[r3base + j * 272];
    fwht16_regs(v);

    // quantize in registers
#pragma unroll
    for (int j = 0; j < 16; j++) {
        float z = v[j] * 0.015625f;
        float t = rintf(z * 4.0f);
        t = fminf(7.0f, fmaxf(-8.0f, t));
        v[j] = t * 0.25f;
    }

    // ---- FWHT #2 ----
#pragma unroll
    for (int j = 0; j < 16; j++) sh[r3base + j * 272] = v[j];
    __syncthreads();

#pragma unroll
    for (int j = 0; j < 16; j++) v[j] = sh[wbase + j];
    fwht16_regs(v);
#pragma unroll
    for (int j = 0; j < 16; j++) sh[wbase + j] = v[j];
    __syncthreads();

#pragma unroll
    for (int j = 0; j < 16; j++) v[j] = sh[r2base + j * 17];
    fwht16_regs(v);
#pragma unroll
    for (int j = 0; j < 16; j++) sh[r2base + j * 17] = v[j];
    __syncthreads();

#pragma unroll
    for (int j = 0; j < 16; j++) v[j] = sh[r3base + j * 272];
    fwht16_regs(v);

    float* orow = out + (size_t)row * N_DIM;
#pragma unroll
    for (int j = 0; j < 12; j++)                      // 12*256 = 3072
        orow[j * 256 + tid] = v[j] * 0.015625f;
}

// ---------------------------------------------------------------------------
extern "C" void kernel_launch(void* const* d_in, const int* in_sizes, int n_in,
                              void* d_out, int out_size)
{
    const float* x = (const float*)d_in[0];   // (4,2048,4096) f32
    const float* W = (const float*)d_in[1];   // (4096,3072) f32
    const float* b = (const float*)d_in[2];   // (3072,) f32
    float* out = (float*)d_out;               // (4,2048,3072) f32

    cudaFuncSetAttribute(gemm_fp16x2, cudaFuncAttributeMaxDynamicSharedMemorySize, DSMEM);

    split_xw_kernel<<<XBLOCKS + WBLOCKS, 256>>>(x, W);
    gemm_fp16x2<<<dim3(N_DIM / 128, M_DIM / 128, 2), 256, DSMEM>>>(b);
    fwht_quant_kernel<<<M_DIM, 256>>>(out);
}

// round 16
// speedup vs baseline: 1.0313x; 1.0305x over previous
#include <cuda_runtime.h>
#include <cuda_fp16.h>
#include <math.h>
#include <stdint.h>

#define M_DIM 8192
#define N_DIM 3072
#define K_DIM 4096
#define PADN  4096

// Scratch (device globals; allocation-free)
__device__ float  g_y [(size_t)M_DIM * N_DIM];                 // 96 MB  (K-half 0 + bias)
__device__ float  g_y2[(size_t)M_DIM * N_DIM];                 // 96 MB  (K-half 1)
__device__ __half g_xs[2ull * (size_t)M_DIM * K_DIM];          // 128 MB: X splits [s][m][k]
__device__ __half g_wt[2ull * (size_t)N_DIM * K_DIM];          // 48 MB:  (64*W)^T splits [s][n][k]

// ---------------------------------------------------------------------------
__device__ __forceinline__ uint32_t smem_u32(const void* p) {
    uint32_t a;
    asm("{ .reg .u64 t; cvta.to.shared.u64 t, %1; cvt.u32.u64 %0, t; }" : "=r"(a) : "l"(p));
    return a;
}
__device__ __forceinline__ void cpa16(uint32_t dst, const void* src) {
    asm volatile("cp.async.cg.shared.global [%0], [%1], 16;" :: "r"(dst), "l"(src) : "memory");
}
#define CP_COMMIT() asm volatile("cp.async.commit_group;" ::: "memory")

#define LDSM_X4(r, addr) \
    asm volatile("ldmatrix.sync.aligned.m8n8.x4.shared.b16 {%0,%1,%2,%3}, [%4];" \
        : "=r"((r)[0]), "=r"((r)[1]), "=r"((r)[2]), "=r"((r)[3]) : "r"(addr))

// fp16 mma, fp32 accumulate: d += a*b
#define MMA_F16(c, a, b0, b1) \
    asm volatile("mma.sync.aligned.m16n8k16.row.col.f32.f16.f16.f32 " \
        "{%0,%1,%2,%3}, {%4,%5,%6,%7}, {%8,%9}, {%0,%1,%2,%3};" \
        : "+f"((c)[0]), "+f"((c)[1]), "+f"((c)[2]), "+f"((c)[3]) \
        : "r"((a)[0]), "r"((a)[1]), "r"((a)[2]), "r"((a)[3]), "r"(b0), "r"(b1))

// fresh chunk: d = a*b + 0
#define MMA_F16_Z(d, a, b0, b1, z) \
    asm volatile("mma.sync.aligned.m16n8k16.row.col.f32.f16.f16.f32 " \
        "{%0,%1,%2,%3}, {%4,%5,%6,%7}, {%8,%9}, {%10,%10,%10,%10};" \
        : "=f"((d)[0]), "=f"((d)[1]), "=f"((d)[2]), "=f"((d)[3]) \
        : "r"((a)[0]), "r"((a)[1]), "r"((a)[2]), "r"((a)[3]), "r"(b0), "r"(b1), "f"(z))

// ldmatrix shared address with SW128 swizzle (defined BEFORE any use)
__device__ __forceinline__ uint32_t lm_addr(uint32_t tbase, int row, int kbyte) {
    uint32_t off = (uint32_t)(row * 128 + kbyte);
    return tbase + (off ^ ((off >> 3) & 0x70));
}

// ---------------------------------------------------------------------------
// Merged prepass: blocks [0, 16384) split X -> 2 fp16 planes;
// blocks [16384, 28672) scale W by 64, split + transpose -> 2 fp16 planes.
// ---------------------------------------------------------------------------
#define XBLOCKS 16384
#define WBLOCKS (128 * 96)            // (K/32) x (N/32)

__global__ __launch_bounds__(256)
void split_xw_kernel(const float* __restrict__ X, const float* __restrict__ W)
{
    __shared__ __half sh[2][32][33];
    const int bid = blockIdx.x;
    const int tid = threadIdx.x;

    if (bid < XBLOCKS) {
        size_t idx = ((size_t)bid * 256 + tid) * 8;
        float4 v0 = *(const float4*)(X + idx);
        float4 v1 = *(const float4*)(X + idx + 4);
        float f[8] = {v0.x, v0.y, v0.z, v0.w, v1.x, v1.y, v1.z, v1.w};
        __half2 p0[4], p1[4];
#pragma unroll
        for (int j = 0; j < 4; j++) {
            float a = f[2*j], b = f[2*j+1];
            __half a0 = __float2half_rn(a), b0 = __float2half_rn(b);
            float ra = a - __half2float(a0), rb = b - __half2float(b0);
            __half a1 = __float2half_rn(ra), b1 = __float2half_rn(rb);
            p0[j] = __halves2half2(a0, b0);
            p1[j] = __halves2half2(a1, b1);
        }
        const size_t MK = (size_t)M_DIM * K_DIM;
        *(float4*)(g_xs + 0 * MK + idx) = *(float4*)p0;
        *(float4*)(g_xs + 1 * MK + idx) = *(float4*)p1;
    } else {
        const int wb = bid - XBLOCKS;
        const int k0 = (wb & 127) * 32;           // 128 k-tiles
        const int n0 = (wb >> 7) * 32;            // 96 n-tiles
        const int tx = tid & 31, ty = tid >> 5;
#pragma unroll
        for (int r = 0; r < 4; r++) {
            int kk = ty + r * 8;
            float w = W[(size_t)(k0 + kk) * N_DIM + n0 + tx] * 64.0f;  // exact scale
            __half b0 = __float2half_rn(w);
            float r1 = w - __half2float(b0);
            __half b1 = __float2half_rn(r1);
            sh[0][kk][tx] = b0; sh[1][kk][tx] = b1;
        }
        __syncthreads();
        const size_t NK = (size_t)N_DIM * K_DIM;
#pragma unroll
        for (int s = 0; s < 2; s++)
#pragma unroll
            for (int r = 0; r < 4; r++) {
                int nn = ty + r * 8;
                g_wt[(size_t)s * NK + (size_t)(n0 + nn) * K_DIM + k0 + tx] = sh[s][tx][nn];
            }
    }
}

// ---------------------------------------------------------------------------
// Persistent GEMM: fp16x2 via mma.sync.m16n8k16, 3 accumulating passes per
// k16 chunk (small passes first, main last), RN FADD drain into fp32 masters.
// 128x128 tile, BK=64, 256 threads (8 warps, 4Mx2N). Grid = #SMs; each CTA
// walks tiles t = bid + j*gridDim.x through ONE flat 3-stage cp.async
// pipeline that never drains across tile boundaries (no per-tile prologue).
// SPLIT-K=2 encoded in the tile index (kh tiles write g_y2, no bias).
// ---------------------------------------------------------------------------
#define GKT 64
#define NKITER_H 32                   // K-tiles per K-half (K/2/GKT)
#define N_TILES_X 24                  // N / 128
#define N_TILES   3072                // 24 * 64 * 2
#define TILE_B 16384                  // 128 rows x 64 fp16 (128B rows, SW128)
#define STG_B  (4 * TILE_B)           // 64 KB (A0,A1,B0,B1)
#define NSTAGE 3
#define DSMEM  (NSTAGE * STG_B)       // 192 KB

__device__ __forceinline__ void decode_tile(int t, int& m0, int& bn0, int& kt0, int& kh)
{
    int nx  = t % N_TILES_X;
    int rem = t / N_TILES_X;          // 0..127
    int my  = rem & 63;
    kh  = rem >> 6;
    m0  = my * 128;
    bn0 = nx * 128;
    kt0 = kh * NKITER_H;
}

__device__ __forceinline__ void load_stage(uint32_t sb, int buf, int kt,
                                           int m0, int bn0, int tid)
{
    const int k0 = kt * GKT;
    const uint32_t base = sb + buf * STG_B;
    const size_t MK = (size_t)M_DIM * K_DIM;
    const size_t NK = (size_t)N_DIM * K_DIM;
#pragma unroll
    for (int t = 0; t < 4; t++) {
        const __half* src = (t < 2)
            ? (g_xs + (size_t)t * MK + (size_t)m0 * K_DIM + k0)
            : (g_wt + (size_t)(t - 2) * NK + (size_t)bn0 * K_DIM + k0);
        const uint32_t tb = base + t * TILE_B;
#pragma unroll
        for (int c = 0; c < 4; c++) {
            int chunk = tid + c * 256;           // 0..1023
            int row = chunk >> 3;
            int c16 = chunk & 7;
            uint32_t off = (uint32_t)(row * 128 + c16 * 16);
            uint32_t sw = off ^ ((off >> 3) & 0x70);   // SW128
            cpa16(tb + sw, src + (size_t)row * K_DIM + c16 * 8);
        }
    }
    CP_COMMIT();
}

__device__ __forceinline__ void load_for(uint32_t sb, int g, int bid, int nsm, int tid)
{
    const int j  = g >> 5;            // tile slot for this CTA
    const int kk = g & 31;            // K-tile within the tile's K-half
    const int t  = bid + j * nsm;
    int m0, bn0, kt0, kh;
    decode_tile(t, m0, bn0, kt0, kh);
    load_stage(sb, g % NSTAGE, kt0 + kk, m0, bn0, tid);
}

__global__ __launch_bounds__(256, 1)
void gemm_fp16x2(const float* __restrict__ Bias)
{
    extern __shared__ char dsm[];
    const int tid = threadIdx.x;
    const int wid = tid >> 5, lid = tid & 31;
    const int wm = wid & 3;            // 4 warps down M (32 rows each)
    const int wn = wid >> 2;           // 2 warps across N (64 cols each)
    const int bid = blockIdx.x;
    const int nsm = gridDim.x;

    const int ntiles = (N_TILES - bid + nsm - 1) / nsm;
    if (ntiles <= 0) return;
    const int total = ntiles * NKITER_H;

    const uint32_t sb = smem_u32(dsm);

    // Prologue (once per CTA, not per tile)
    load_for(sb, 0, bid, nsm, tid);
    load_for(sb, 1, bid, nsm, tid);

    float acc[2][8][4];
#pragma unroll
    for (int mb = 0; mb < 2; mb++)
#pragma unroll
        for (int nb = 0; nb < 8; nb++)
#pragma unroll
            for (int q = 0; q < 4; q++) acc[mb][nb][q] = 0.0f;

    const float fzero = 0.0f;

    const int g = lid >> 3, r = lid & 7;
    const int a_row = wm * 32 + (g & 1) * 8 + r;   // + mb*16
    const int a_kg  = (g >> 1) * 16;               // + kb
    const int b_row = wn * 64 + (g >> 1) * 8 + r;  // + np*16
    const int b_kg  = (g & 1) * 16;                // + kb

    const int cl = 2 * (lid & 3);
    const int rl = lid >> 2;

    for (int gi = 0; gi < total; gi++) {
        if (gi < total - 1) asm volatile("cp.async.wait_group 1;" ::: "memory");
        else                asm volatile("cp.async.wait_group 0;" ::: "memory");
        __syncthreads();

        if (gi + 2 < total) load_for(sb, gi + 2, bid, nsm, tid);

        const uint32_t base = sb + (gi % NSTAGE) * STG_B;

#pragma unroll
        for (int k16 = 0; k16 < 4; k16++) {
            const int kb = k16 * 32;               // bytes
            uint32_t af[2][2][4], bfr[2][4][4];
#pragma unroll
            for (int s = 0; s < 2; s++) {
#pragma unroll
                for (int mb = 0; mb < 2; mb++)
                    LDSM_X4(af[s][mb], lm_addr(base + s * TILE_B,
                                               a_row + mb * 16, kb + a_kg));
#pragma unroll
                for (int np = 0; np < 4; np++)
                    LDSM_X4(bfr[s][np], lm_addr(base + (2 + s) * TILE_B,
                                                b_row + np * 16, kb + b_kg));
            }
#pragma unroll
            for (int mb = 0; mb < 2; mb++)
#pragma unroll
                for (int np = 0; np < 4; np++) {
                    float ch[8];
                    // pass order: (x0,w1), (x1,w0), then main (x0,w0) LAST
                    MMA_F16_Z(ch,     af[0][mb], bfr[1][np][0], bfr[1][np][1], fzero);
                    MMA_F16_Z(ch + 4, af[0][mb], bfr[1][np][2], bfr[1][np][3], fzero);
                    MMA_F16(ch,     af[1][mb], bfr[0][np][0], bfr[0][np][1]);
                    MMA_F16(ch + 4, af[1][mb], bfr[0][np][2], bfr[0][np][3]);
                    MMA_F16(ch,     af[0][mb], bfr[0][np][0], bfr[0][np][1]);
                    MMA_F16(ch + 4, af[0][mb], bfr[0][np][2], bfr[0][np][3]);
                    // RN drain into master accumulators
#pragma unroll
                    for (int q = 0; q < 4; q++) {
                        acc[mb][2*np][q]     += ch[q];
                        acc[mb][2*np + 1][q] += ch[4 + q];
                    }
                }
        }

        // Tile boundary: epilogue + accumulator reset (prefetch already in flight)
        if ((gi & 31) == 31) {
            const int t = bid + (gi >> 5) * nsm;
            int m0, bn0, kt0, kh;
            decode_tile(t, m0, bn0, kt0, kh);
            float* dstbuf = kh ? g_y2 : g_y;
            const int m0g = m0 + wm * 32;
            const int n0g = bn0 + wn * 64;
#pragma unroll
            for (int nb = 0; nb < 8; nb++) {
                const int col = n0g + nb * 8 + cl;
                float2 b2 = {0.0f, 0.0f};
                if (kh == 0) b2 = *(const float2*)(Bias + col);
#pragma unroll
                for (int mb = 0; mb < 2; mb++) {
                    const int row = m0g + mb * 16 + rl;
                    float2 v0 = { acc[mb][nb][0] * 0.015625f + b2.x,
                                  acc[mb][nb][1] * 0.015625f + b2.y };
                    float2 v1 = { acc[mb][nb][2] * 0.015625f + b2.x,
                                  acc[mb][nb][3] * 0.015625f + b2.y };
                    *(float2*)&dstbuf[(size_t)row * N_DIM + col]       = v0;
                    *(float2*)&dstbuf[(size_t)(row + 8) * N_DIM + col] = v1;
                }
            }
#pragma unroll
            for (int mb = 0; mb < 2; mb++)
#pragma unroll
                for (int nb = 0; nb < 8; nb++)
#pragma unroll
                    for (int q = 0; q < 4; q++) acc[mb][nb][q] = 0.0f;
        }
    }
}

// ---------------------------------------------------------------------------
// Radix-16 FWHT(4096) -> quantize -> FWHT(4096) -> slice 3072.
// Loads combine the two split-K halves: y = g_y + g_y2 (RN).
// ---------------------------------------------------------------------------
__device__ __forceinline__ void fwht16_regs(float v[16]) {
#pragma unroll
    for (int h = 1; h < 16; h <<= 1) {
#pragma unroll
        for (int p = 0; p < 8; p++) {
            int i = ((p & ~(h - 1)) << 1) | (p & (h - 1));
            float a = v[i], c = v[i + h];
            v[i] = a + c;
            v[i + h] = a - c;
        }
    }
}

__global__ __launch_bounds__(256, 8)
void fwht_quant_kernel(float* __restrict__ out)
{
    __shared__ float sh[4352];          // 4096 + 256 pad
    const int row = blockIdx.x;
    const int tid = threadIdx.x;
    const float* yrow0 = g_y  + (size_t)row * N_DIM;
    const float* yrow1 = g_y2 + (size_t)row * N_DIM;

    float v[16];

    // ---- FWHT #1 ----
    if (tid < 192) {
#pragma unroll
        for (int j = 0; j < 16; j += 4) {
            float4 t4 = *(const float4*)(yrow0 + tid * 16 + j);
            float4 u4 = *(const float4*)(yrow1 + tid * 16 + j);
            v[j]   = t4.x + u4.x; v[j+1] = t4.y + u4.y;
            v[j+2] = t4.z + u4.z; v[j+3] = t4.w + u4.w;
        }
    } else {
#pragma unroll
        for (int j = 0; j < 16; j++) v[j] = 0.0f;
    }
    fwht16_regs(v);

    const int wbase = tid * 17;
#pragma unroll
    for (int j = 0; j < 16; j++) sh[wbase + j] = v[j];
    __syncthreads();

    const int a = tid >> 4, c = tid & 15;
    const int r2base = a * 272 + c;
#pragma unroll
    for (int j = 0; j < 16; j++) v[j] = sh[r2base + j * 17];
    fwht16_regs(v);
#pragma unroll
    for (int j = 0; j < 16; j++) sh[r2base + j * 17] = v[j];
    __syncthreads();

    const int r3base = (tid >> 4) * 17 + c;
#pragma unroll
    for (int j = 0; j < 16; j++) v[j] = sh[r3base + j * 272];
    fwht16_regs(v);

    // quantize in registers
#pragma unroll
    for (int j = 0; j < 16; j++) {
        float z = v[j] * 0.015625f;
        float t = rintf(z * 4.0f);
        t = fminf(7.0f, fmaxf(-8.0f, t));
        v[j] = t * 0.25f;
    }

    // ---- FWHT #2 ----
#pragma unroll
    for (int j = 0; j < 16; j++) sh[r3base + j * 272] = v[j];
    __syncthreads();

#pragma unroll
    for (int j = 0; j < 16; j++) v[j] = sh[wbase + j];
    fwht16_regs(v);
#pragma unroll
    for (int j = 0; j < 16; j++) sh[wbase + j] = v[j];
    __syncthreads();

#pragma unroll
    for (int j = 0; j < 16; j++) v[j] = sh[r2base + j * 17];
    fwht16_regs(v);
#pragma unroll
    for (int j = 0; j < 16; j++) sh[r2base + j * 17] = v[j];
    __syncthreads();

#pragma unroll
    for (int j = 0; j < 16; j++) v[j] = sh[r3base + j * 272];
    fwht16_regs(v);

    float* orow = out + (size_t)row * N_DIM;
#pragma unroll
    for (int j = 0; j < 12; j++)                      // 12*256 = 3072
        orow[j * 256 + tid] = v[j] * 0.015625f;
}

// ---------------------------------------------------------------------------
extern "C" void kernel_launch(void* const* d_in, const int* in_sizes, int n_in,
                              void* d_out, int out_size)
{
    const float* x = (const float*)d_in[0];   // (4,2048,4096) f32
    const float* W = (const float*)d_in[1];   // (4096,3072) f32
    const float* b = (const float*)d_in[2];   // (3072,) f32
    float* out = (float*)d_out;               // (4,2048,3072) f32

    int nsm = 148;
    cudaDeviceGetAttribute(&nsm, cudaDevAttrMultiProcessorCount, 0);

    cudaFuncSetAttribute(gemm_fp16x2, cudaFuncAttributeMaxDynamicSharedMemorySize, DSMEM);

    split_xw_kernel<<<XBLOCKS + WBLOCKS, 256>>>(x, W);
    gemm_fp16x2<<<nsm, 256, DSMEM>>>(b);
    fwht_quant_kernel<<<M_DIM, 256>>>(out);
}